// round 1
// baseline (speedup 1.0000x reference)
#include <cuda_runtime.h>
#include <cuda_bf16.h>

// Problem dims (fixed by setup_inputs)
#define Nn 16
#define Cc 4
#define Hh 256
#define Ww 256
#define HW  (Hh * Ww)       // 65536
#define CHW (Cc * HW)       // 262144
#define TOT (Nn * CHW)      // 4194304
#define INFV 1.0e10f

// Scratch (device globals: no allocation allowed)
__device__ float  g_f1[TOT];   // after C pass
__device__ float  g_f2[TOT];   // after H pass
__device__ double g_acc[2];    // num, den

// ---------------------------------------------------------------------------
__global__ void k_zero() {
    g_acc[0] = 0.0;
    g_acc[1] = 0.0;
}

// ---------------------------------------------------------------------------
// C pass: per (n,h,w) column of 4 classes. f1[c] = min_{c'} (c-c')^2 + (target!=0 ? 0 : INF)
// Costs are ordered by |c-c'|, so nested selects give the exact min.
__global__ void k_cpass(const int* __restrict__ tgt) {
    int idx = blockIdx.x * blockDim.x + threadIdx.x;   // over N*H*W = 1048576
    if (idx >= Nn * HW) return;
    int n  = idx >> 16;            // / HW
    int hw = idx & (HW - 1);
    int base = n * CHW + hw;

    bool t0 = tgt[base          ] != 0;
    bool t1 = tgt[base +     HW ] != 0;
    bool t2 = tgt[base + 2 * HW ] != 0;
    bool t3 = tgt[base + 3 * HW ] != 0;

    float f0 = t0 ? 0.f : (t1 ? 1.f : (t2 ? 4.f : (t3 ? 9.f : INFV)));
    float f1 = t1 ? 0.f : ((t0 || t2) ? 1.f : (t3 ? 4.f : INFV));
    float f2 = t2 ? 0.f : ((t1 || t3) ? 1.f : (t0 ? 4.f : INFV));
    float f3 = t3 ? 0.f : (t2 ? 1.f : (t1 ? 4.f : (t0 ? 9.f : INFV)));

    g_f1[base         ] = f0;
    g_f1[base +     HW] = f1;
    g_f1[base + 2 * HW] = f2;
    g_f1[base + 3 * HW] = f3;
}

// ---------------------------------------------------------------------------
// H pass: out[h] = min_j (h-j)^2 + f1[j] along H.
// Window radius 3; any candidate outside the window costs >= 16, so the
// windowed min is EXACT whenever it is <= 16. Otherwise full-scan fallback.
__global__ void k_hpass() {
    int idx = blockIdx.x * blockDim.x + threadIdx.x;   // over TOT
    if (idx >= TOT) return;
    int w  = idx & 255;
    int h  = (idx >> 8) & 255;
    int nc = idx >> 16;
    const float* __restrict__ col = g_f1 + nc * HW + w;   // element j at col[j*Ww]

    float m = INFV;
#pragma unroll
    for (int d = -3; d <= 3; d++) {
        int j = h + d;
        if (j >= 0 && j < Hh)
            m = fminf(m, col[j * Ww] + (float)(d * d));
    }
    if (m > 16.0f) {   // rare exact fallback
        m = INFV;
        for (int j = 0; j < Hh; j++) {
            float dj = (float)(h - j);
            m = fminf(m, fmaf(dj, dj, col[j * Ww]));
        }
    }
    g_f2[idx] = m;
}

// ---------------------------------------------------------------------------
// W pass fused with softmax + reduction.
// One thread per (n,h,w): computes dist for all 4 classes, softmax over C,
// accumulates num = sum(p*dist), den = sum(dist).
__global__ void k_wpass(const float* __restrict__ pred) {
    int idx = blockIdx.x * blockDim.x + threadIdx.x;   // over N*H*W
    float num = 0.f, den = 0.f;
    if (idx < Nn * HW) {
        int w = idx & 255;
        int h = (idx >> 8) & 255;
        int n = idx >> 16;
        int base = n * CHW + (h << 8) + w;   // c = 0 element

        float dist[4];
        float x[4];
#pragma unroll
        for (int c = 0; c < 4; c++) {
            const float* __restrict__ row = g_f2 + base + c * HW - w;  // row[j], j in [0,256)
            float m = INFV;
#pragma unroll
            for (int d = -3; d <= 3; d++) {
                int j = w + d;
                if (j >= 0 && j < Ww)
                    m = fminf(m, row[j] + (float)(d * d));
            }
            if (m > 16.0f) {   // rare exact fallback
                m = INFV;
                for (int j = 0; j < Ww; j++) {
                    float dj = (float)(w - j);
                    m = fminf(m, fmaf(dj, dj, row[j]));
                }
            }
            dist[c] = sqrtf(m);
            x[c] = pred[base + c * HW];
        }

        float mx = fmaxf(fmaxf(x[0], x[1]), fmaxf(x[2], x[3]));
        float e0 = __expf(x[0] - mx);
        float e1 = __expf(x[1] - mx);
        float e2 = __expf(x[2] - mx);
        float e3 = __expf(x[3] - mx);
        float inv = 1.0f / (e0 + e1 + e2 + e3);
        num = (e0 * dist[0] + e1 * dist[1] + e2 * dist[2] + e3 * dist[3]) * inv;
        den = dist[0] + dist[1] + dist[2] + dist[3];
    }

    // warp reduce
#pragma unroll
    for (int o = 16; o; o >>= 1) {
        num += __shfl_xor_sync(0xFFFFFFFFu, num, o);
        den += __shfl_xor_sync(0xFFFFFFFFu, den, o);
    }
    if ((threadIdx.x & 31) == 0) {
        atomicAdd(&g_acc[0], (double)num);
        atomicAdd(&g_acc[1], (double)den);
    }
}

// ---------------------------------------------------------------------------
__global__ void k_final(float* __restrict__ out) {
    out[0] = (float)(g_acc[0] / (g_acc[1] + 1e-10));
}

// ---------------------------------------------------------------------------
extern "C" void kernel_launch(void* const* d_in, const int* in_sizes, int n_in,
                              void* d_out, int out_size) {
    const float* pred = (const float*)d_in[0];
    const int*   tgt  = (const int*)d_in[1];
    float*       out  = (float*)d_out;

    k_zero<<<1, 1>>>();
    k_cpass<<<(Nn * HW) / 256, 256>>>(tgt);
    k_hpass<<<TOT / 256, 256>>>();
    k_wpass<<<(Nn * HW) / 256, 256>>>(pred);
    k_final<<<1, 1>>>(out);
}

// round 2
// speedup vs baseline: 3.2584x; 3.2584x over previous
#include <cuda_runtime.h>
#include <cuda_bf16.h>

// Problem dims (fixed by setup_inputs)
#define Nn 16
#define Cc 4
#define Hh 256
#define Ww 256
#define HW  (Hh * Ww)       // 65536
#define CHW (Cc * HW)       // 262144
#define TOT (Nn * CHW)      // 4194304
#define INFV 1.0e10f
#define NBLK_W (Nn * Hh)    // 4096 blocks in w-pass

// Scratch (device globals: no allocation allowed)
__device__ float  g_f1[TOT];            // after C pass
__device__ float  g_f2[TOT];            // after H pass
__device__ float2 g_part[NBLK_W];       // per-block (num, den) partials

// ---------------------------------------------------------------------------
// C pass: per (n,h,w) column of 4 classes. f1[c] = min_{c'} (c-c')^2 + (t[c']!=0 ? 0 : INF)
// Costs ordered by |c-c'| -> nested selects give the exact min.
__global__ void k_cpass(const int* __restrict__ tgt) {
    int idx = blockIdx.x * blockDim.x + threadIdx.x;   // over N*H*W = 1048576
    int n  = idx >> 16;
    int hw = idx & (HW - 1);
    int base = n * CHW + hw;

    bool t0 = tgt[base          ] != 0;
    bool t1 = tgt[base +     HW ] != 0;
    bool t2 = tgt[base + 2 * HW ] != 0;
    bool t3 = tgt[base + 3 * HW ] != 0;

    float f0 = t0 ? 0.f : (t1 ? 1.f : (t2 ? 4.f : (t3 ? 9.f : INFV)));
    float f1 = t1 ? 0.f : ((t0 || t2) ? 1.f : (t3 ? 4.f : INFV));
    float f2 = t2 ? 0.f : ((t1 || t3) ? 1.f : (t0 ? 4.f : INFV));
    float f3 = t3 ? 0.f : (t2 ? 1.f : (t1 ? 4.f : (t0 ? 9.f : INFV)));

    g_f1[base         ] = f0;
    g_f1[base +     HW] = f1;
    g_f1[base + 2 * HW] = f2;
    g_f1[base + 3 * HW] = f3;
}

// ---------------------------------------------------------------------------
// H pass: out[h] = min_j (h-j)^2 + f1[j] along H, tiled in shared memory.
// Block = (n*c, 32-wide w tile), full H column in smem (256x32 floats = 32KB).
// Window radius 3 is exact when min <= 16 (outside-window cost >= 16);
// rare fallback scans the full smem column.
__global__ void k_hpass() {
    __shared__ float tile[256 * 32];
    int b     = blockIdx.x;          // nc*8 + wtile
    int nc    = b >> 3;
    int wbase = (b & 7) << 5;
    int tid   = threadIdx.x;
    const float* __restrict__ src = g_f1 + nc * HW + wbase;

#pragma unroll
    for (int rep = 0; rep < 32; rep++) {
        int idx = rep * 256 + tid;                 // == h*32 + w
        int h = idx >> 5, w = idx & 31;
        tile[idx] = src[h * 256 + w];              // warp loads one 128B row chunk
    }
    __syncthreads();

    float* __restrict__ dst = g_f2 + nc * HW + wbase;
#pragma unroll 4
    for (int rep = 0; rep < 32; rep++) {
        int idx = rep * 256 + tid;
        int h = idx >> 5, w = idx & 31;
        float m = INFV;
#pragma unroll
        for (int d = -3; d <= 3; d++) {
            int j = h + d;
            if (j >= 0 && j < Hh)
                m = fminf(m, tile[j * 32 + w] + (float)(d * d));
        }
        if (m > 16.0f) {                            // rare exact fallback (smem scan)
            m = INFV;
            for (int j = 0; j < Hh; j++) {
                float dj = (float)(h - j);
                m = fminf(m, fmaf(dj, dj, tile[j * 32 + w]));
            }
        }
        dst[h * 256 + w] = m;
    }
}

// ---------------------------------------------------------------------------
// W pass fused with softmax + block reduction. Block = one (n,h) row, 256 threads.
// Rows of g_f2 for all 4 classes staged in smem; window taps conflict-free.
// Per-block partial (num, den) written to g_part — NO contended atomics.
__global__ void k_wpass(const float* __restrict__ pred) {
    __shared__ float srow[4][256];
    __shared__ float rnum[8], rden[8];
    int nh = blockIdx.x;                 // n*256 + h
    int w  = threadIdx.x;
    int n  = nh >> 8, h = nh & 255;
    int base = n * CHW + (h << 8);

#pragma unroll
    for (int c = 0; c < 4; c++)
        srow[c][w] = g_f2[base + c * HW + w];
    __syncthreads();

    float dist[4], x[4];
#pragma unroll
    for (int c = 0; c < 4; c++) {
        float m = INFV;
#pragma unroll
        for (int d = -3; d <= 3; d++) {
            int j = w + d;
            if (j >= 0 && j < Ww)
                m = fminf(m, srow[c][j] + (float)(d * d));
        }
        if (m > 16.0f) {                 // rare exact fallback (smem scan)
            m = INFV;
            for (int j = 0; j < Ww; j++) {
                float dj = (float)(w - j);
                m = fminf(m, fmaf(dj, dj, srow[c][j]));
            }
        }
        dist[c] = sqrtf(m);
        x[c] = pred[base + c * HW + w];
    }

    float mx = fmaxf(fmaxf(x[0], x[1]), fmaxf(x[2], x[3]));
    float e0 = __expf(x[0] - mx);
    float e1 = __expf(x[1] - mx);
    float e2 = __expf(x[2] - mx);
    float e3 = __expf(x[3] - mx);
    float inv = 1.0f / (e0 + e1 + e2 + e3);
    float num = (e0 * dist[0] + e1 * dist[1] + e2 * dist[2] + e3 * dist[3]) * inv;
    float den = dist[0] + dist[1] + dist[2] + dist[3];

    // warp reduce
#pragma unroll
    for (int o = 16; o; o >>= 1) {
        num += __shfl_xor_sync(0xFFFFFFFFu, num, o);
        den += __shfl_xor_sync(0xFFFFFFFFu, den, o);
    }
    int lane = w & 31, wid = w >> 5;
    if (lane == 0) { rnum[wid] = num; rden[wid] = den; }
    __syncthreads();
    if (wid == 0) {
        num = (lane < 8) ? rnum[lane] : 0.f;
        den = (lane < 8) ? rden[lane] : 0.f;
#pragma unroll
        for (int o = 4; o; o >>= 1) {
            num += __shfl_xor_sync(0xFFFFFFFFu, num, o);
            den += __shfl_xor_sync(0xFFFFFFFFu, den, o);
        }
        if (lane == 0) g_part[nh] = make_float2(num, den);
    }
}

// ---------------------------------------------------------------------------
// Final: one block reduces 4096 float2 partials in double, writes the scalar.
__global__ void k_reduce(float* __restrict__ out) {
    __shared__ double snum[8], sden[8];
    int tid = threadIdx.x;
    double num = 0.0, den = 0.0;
#pragma unroll
    for (int r = 0; r < NBLK_W / 256; r++) {
        float2 p = g_part[r * 256 + tid];
        num += (double)p.x;
        den += (double)p.y;
    }
#pragma unroll
    for (int o = 16; o; o >>= 1) {
        num += __shfl_xor_sync(0xFFFFFFFFu, num, o);
        den += __shfl_xor_sync(0xFFFFFFFFu, den, o);
    }
    int lane = tid & 31, wid = tid >> 5;
    if (lane == 0) { snum[wid] = num; sden[wid] = den; }
    __syncthreads();
    if (wid == 0) {
        num = (lane < 8) ? snum[lane] : 0.0;
        den = (lane < 8) ? sden[lane] : 0.0;
#pragma unroll
        for (int o = 4; o; o >>= 1) {
            num += __shfl_xor_sync(0xFFFFFFFFu, num, o);
            den += __shfl_xor_sync(0xFFFFFFFFu, den, o);
        }
        if (lane == 0) out[0] = (float)(num / (den + 1e-10));
    }
}

// ---------------------------------------------------------------------------
extern "C" void kernel_launch(void* const* d_in, const int* in_sizes, int n_in,
                              void* d_out, int out_size) {
    const float* pred = (const float*)d_in[0];
    const int*   tgt  = (const int*)d_in[1];
    float*       out  = (float*)d_out;

    k_cpass<<<(Nn * HW) / 256, 256>>>(tgt);
    k_hpass<<<Nn * Cc * (Ww / 32), 256>>>();
    k_wpass<<<NBLK_W, 256>>>(pred);
    k_reduce<<<1, 256>>>(out);
}

// round 3
// speedup vs baseline: 3.6410x; 1.1174x over previous
#include <cuda_runtime.h>
#include <cuda_bf16.h>

// Problem dims (fixed by setup_inputs)
#define Nn 16
#define Cc 4
#define Hh 256
#define Ww 256
#define HW  (Hh * Ww)       // 65536
#define CHW (Cc * HW)       // 262144
#define TOT (Nn * CHW)      // 4194304
#define INFV 1.0e10f
#define NBLK_M (Nn * Hh)    // 4096 blocks in main pass

// Scratch (device globals: no allocation allowed)
__device__ unsigned char g_f1[TOT];     // after C pass: {0,1,4,9, 255=INF}
__device__ float2 g_part[NBLK_M];       // per-block (num, den) partials
__device__ unsigned int g_ctr;          // last-block counter (reset by k_cpass)

// ---------------------------------------------------------------------------
// C pass: f1[c] = min_{c'} (c-c')^2 + (t[c']!=0 ? 0 : INF), packed u8.
// int4 loads (4 w positions), uchar4 stores. Also resets the main-pass counter.
__global__ void k_cpass(const int* __restrict__ tgt) {
    int idx = blockIdx.x * blockDim.x + threadIdx.x;   // over N*H*W/4 = 262144
    if (idx == 0) g_ctr = 0u;
    int n   = idx >> 14;
    int rem = idx & 16383;           // plane offset / 4
    int base = n * CHW + (rem << 2);

    int4 a0 = *(const int4*)(tgt + base         );
    int4 a1 = *(const int4*)(tgt + base +     HW);
    int4 a2 = *(const int4*)(tgt + base + 2 * HW);
    int4 a3 = *(const int4*)(tgt + base + 3 * HW);

    uchar4 o0, o1, o2, o3;
#pragma unroll
    for (int k = 0; k < 4; k++) {
        bool t0 = ((&a0.x)[k]) != 0;
        bool t1 = ((&a1.x)[k]) != 0;
        bool t2 = ((&a2.x)[k]) != 0;
        bool t3 = ((&a3.x)[k]) != 0;
        unsigned char f0 = t0 ? 0 : (t1 ? 1 : (t2 ? 4 : (t3 ? 9 : 255)));
        unsigned char f1 = t1 ? 0 : ((t0 || t2) ? 1 : (t3 ? 4 : 255));
        unsigned char f2 = t2 ? 0 : ((t1 || t3) ? 1 : (t0 ? 4 : 255));
        unsigned char f3 = t3 ? 0 : (t2 ? 1 : (t1 ? 4 : (t0 ? 9 : 255)));
        (&o0.x)[k] = f0; (&o1.x)[k] = f1; (&o2.x)[k] = f2; (&o3.x)[k] = f3;
    }
    *(uchar4*)(g_f1 + base         ) = o0;
    *(uchar4*)(g_f1 + base +     HW) = o1;
    *(uchar4*)(g_f1 + base + 2 * HW) = o2;
    *(uchar4*)(g_f1 + base + 3 * HW) = o3;
}

// ---------------------------------------------------------------------------
__device__ __forceinline__ float dec(unsigned char v) {
    return (v == 255) ? INFV : (float)v;
}

// ---------------------------------------------------------------------------
// Main pass: block = one (n,h) row, 256 threads (one per w).
// Phase 1: build exact f2 row (H-direction min-plus) in smem from f1 rows h±3
//          (window exact when min<=16; rare fallback scans the gmem column).
// Phase 2: W-direction window from smem + softmax over C + block reduction.
// Phase 3: threadfence + counter; last block reduces all partials, writes out.
__global__ void k_main(const float* __restrict__ pred, float* __restrict__ out) {
    __shared__ float f2row[4][256];
    __shared__ float rnum[8], rden[8];
    __shared__ bool  s_last;

    int nh = blockIdx.x;                 // n*256 + h
    int w  = threadIdx.x;
    int n  = nh >> 8, h = nh & 255;
    int base = n * CHW + (h << 8);

    // ---- Phase 1: H-direction ----
#pragma unroll
    for (int c = 0; c < 4; c++) {
        const unsigned char* __restrict__ pc = g_f1 + n * CHW + c * HW + w; // [j<<8]
        float m = INFV;
#pragma unroll
        for (int d = -3; d <= 3; d++) {
            int j = h + d;
            if (j >= 0 && j < Hh)
                m = fminf(m, dec(__ldg(pc + (j << 8))) + (float)(d * d));
        }
        if (m > 16.0f) {                 // rare exact fallback: full gmem column
            m = INFV;
            for (int j = 0; j < Hh; j++) {
                float dj = (float)(h - j);
                m = fminf(m, fmaf(dj, dj, dec(__ldg(pc + (j << 8)))));
            }
        }
        f2row[c][w] = m;
    }
    __syncthreads();

    // ---- Phase 2: W-direction + softmax ----
    float dist[4], x[4];
#pragma unroll
    for (int c = 0; c < 4; c++) {
        float m = INFV;
#pragma unroll
        for (int d = -3; d <= 3; d++) {
            int j = w + d;
            if (j >= 0 && j < Ww)
                m = fminf(m, f2row[c][j] + (float)(d * d));
        }
        if (m > 16.0f) {                 // rare exact fallback: smem row scan
            m = INFV;
            for (int j = 0; j < Ww; j++) {
                float dj = (float)(w - j);
                m = fminf(m, fmaf(dj, dj, f2row[c][j]));
            }
        }
        dist[c] = sqrtf(m);
        x[c] = pred[base + c * HW + w];
    }

    float mx = fmaxf(fmaxf(x[0], x[1]), fmaxf(x[2], x[3]));
    float e0 = __expf(x[0] - mx);
    float e1 = __expf(x[1] - mx);
    float e2 = __expf(x[2] - mx);
    float e3 = __expf(x[3] - mx);
    float inv = 1.0f / (e0 + e1 + e2 + e3);
    float num = (e0 * dist[0] + e1 * dist[1] + e2 * dist[2] + e3 * dist[3]) * inv;
    float den = dist[0] + dist[1] + dist[2] + dist[3];

    // block reduce (warp shuffles + smem)
#pragma unroll
    for (int o = 16; o; o >>= 1) {
        num += __shfl_xor_sync(0xFFFFFFFFu, num, o);
        den += __shfl_xor_sync(0xFFFFFFFFu, den, o);
    }
    int lane = w & 31, wid = w >> 5;
    if (lane == 0) { rnum[wid] = num; rden[wid] = den; }
    __syncthreads();
    if (wid == 0) {
        num = (lane < 8) ? rnum[lane] : 0.f;
        den = (lane < 8) ? rden[lane] : 0.f;
#pragma unroll
        for (int o = 4; o; o >>= 1) {
            num += __shfl_xor_sync(0xFFFFFFFFu, num, o);
            den += __shfl_xor_sync(0xFFFFFFFFu, den, o);
        }
        if (lane == 0) g_part[nh] = make_float2(num, den);
    }

    // ---- Phase 3: last-block final reduction ----
    __threadfence();
    if (threadIdx.x == 0) {
        unsigned int prev = atomicAdd(&g_ctr, 1u);
        s_last = (prev == (unsigned int)(NBLK_M - 1));
    }
    __syncthreads();
    if (!s_last) return;

    __shared__ double snum[8], sden[8];
    double dn = 0.0, dd = 0.0;
#pragma unroll
    for (int r = 0; r < NBLK_M / 256; r++) {
        float2 p = g_part[r * 256 + threadIdx.x];
        dn += (double)p.x;
        dd += (double)p.y;
    }
#pragma unroll
    for (int o = 16; o; o >>= 1) {
        dn += __shfl_xor_sync(0xFFFFFFFFu, dn, o);
        dd += __shfl_xor_sync(0xFFFFFFFFu, dd, o);
    }
    if (lane == 0) { snum[wid] = dn; sden[wid] = dd; }
    __syncthreads();
    if (wid == 0) {
        dn = (lane < 8) ? snum[lane] : 0.0;
        dd = (lane < 8) ? sden[lane] : 0.0;
#pragma unroll
        for (int o = 4; o; o >>= 1) {
            dn += __shfl_xor_sync(0xFFFFFFFFu, dn, o);
            dd += __shfl_xor_sync(0xFFFFFFFFu, dd, o);
        }
        if (lane == 0) out[0] = (float)(dn / (dd + 1e-10));
    }
}

// ---------------------------------------------------------------------------
extern "C" void kernel_launch(void* const* d_in, const int* in_sizes, int n_in,
                              void* d_out, int out_size) {
    const float* pred = (const float*)d_in[0];
    const int*   tgt  = (const int*)d_in[1];
    float*       out  = (float*)d_out;

    k_cpass<<<(Nn * HW / 4) / 256, 256>>>(tgt);
    k_main<<<NBLK_M, 256>>>(pred, out);
}

// round 4
// speedup vs baseline: 4.6819x; 1.2859x over previous
#include <cuda_runtime.h>
#include <cuda_bf16.h>

// Problem dims (fixed by setup_inputs)
#define Nn 16
#define Cc 4
#define Hh 256
#define Ww 256
#define HW  (Hh * Ww)       // 65536
#define CHW (Cc * HW)       // 262144
#define TOT (Nn * CHW)      // 4194304
#define INFV 1.0e10f
#define NBLK 1024           // main-pass blocks (4 rows each)

// Scratch (device globals: no allocation allowed)
__device__ unsigned char g_f1[TOT];     // after C pass: {0,1,4,9, 255=INF}
__device__ float2 g_part[NBLK];         // per-block (num, den) partials
__device__ unsigned int g_ctr;          // last-block counter (reset by k_cpass)

// ---------------------------------------------------------------------------
// C pass: f1[c] = min_{c'} (c-c')^2 + (t[c']!=0 ? 0 : INF), packed u8.
__global__ void k_cpass(const int* __restrict__ tgt) {
    int idx = blockIdx.x * blockDim.x + threadIdx.x;   // over N*H*W/4
    if (idx == 0) g_ctr = 0u;
    int n   = idx >> 14;
    int rem = idx & 16383;
    int base = n * CHW + (rem << 2);

    int4 a0 = *(const int4*)(tgt + base         );
    int4 a1 = *(const int4*)(tgt + base +     HW);
    int4 a2 = *(const int4*)(tgt + base + 2 * HW);
    int4 a3 = *(const int4*)(tgt + base + 3 * HW);

    uchar4 o0, o1, o2, o3;
#pragma unroll
    for (int k = 0; k < 4; k++) {
        bool t0 = ((&a0.x)[k]) != 0;
        bool t1 = ((&a1.x)[k]) != 0;
        bool t2 = ((&a2.x)[k]) != 0;
        bool t3 = ((&a3.x)[k]) != 0;
        (&o0.x)[k] = t0 ? 0 : (t1 ? 1 : (t2 ? 4 : (t3 ? 9 : 255)));
        (&o1.x)[k] = t1 ? 0 : ((t0 || t2) ? 1 : (t3 ? 4 : 255));
        (&o2.x)[k] = t2 ? 0 : ((t1 || t3) ? 1 : (t0 ? 4 : 255));
        (&o3.x)[k] = t3 ? 0 : (t2 ? 1 : (t1 ? 4 : (t0 ? 9 : 255)));
    }
    *(uchar4*)(g_f1 + base         ) = o0;
    *(uchar4*)(g_f1 + base +     HW) = o1;
    *(uchar4*)(g_f1 + base + 2 * HW) = o2;
    *(uchar4*)(g_f1 + base + 3 * HW) = o3;
}

// ---------------------------------------------------------------------------
__device__ __forceinline__ float f1_at(int n, int c, int h, int w) {
    unsigned char v = g_f1[((n * Cc + c) << 16) + (h << 8) + w];
    return (v == 255u) ? INFV : (float)v;
}

// Exact H-direction transform at one (n,c,h,w): window + rare full column scan.
__device__ float exact_f2(int n, int c, int h, int w) {
    float m = INFV;
    int j0 = h - 3 < 0 ? 0 : h - 3;
    int j1 = h + 3 > 255 ? 255 : h + 3;
    for (int j = j0; j <= j1; j++) {
        float dj = (float)(j - h);
        m = fminf(m, fmaf(dj, dj, f1_at(n, c, j, w)));
    }
    if (m > 16.0f) {
        m = INFV;
        for (int j = 0; j < Hh; j++) {
            float dj = (float)(j - h);
            m = fminf(m, fmaf(dj, dj, f1_at(n, c, j, w)));
        }
    }
    return m;
}

// ---------------------------------------------------------------------------
// Main pass. Block = 4 consecutive (n,h) rows x 64 threads; thread = 4 w pixels.
// Packed-u8 SIMD min-plus (vaddus4/vminu4): exact whenever byte <= 16
// (outside-window cost >= 16; INF saturates at 255 and never wins a <=16 min).
__global__ void __launch_bounds__(256) k_main(const float* __restrict__ pred,
                                              float* __restrict__ out) {
    __shared__ unsigned int s_f2[4][4][64];   // [row][class][word]
    __shared__ float sq_tab[20];
    __shared__ float rnum[8], rden[8];
    __shared__ bool  s_last;

    int tid = threadIdx.x;
    int r = tid >> 6, t = tid & 63;
    int nh = (blockIdx.x << 2) + r;           // n*256 + h
    int n = nh >> 8, h = nh & 255;
    int w0 = t << 2;

    if (tid < 20) sq_tab[tid] = sqrtf((float)tid);

    const unsigned int c1 = 0x01010101u, c4 = 0x04040404u, c9 = 0x09090909u;
    const unsigned int cI = 0xFFFFFFFFu, cT = 0x10101010u;

    // ---- Phase 1: H-direction (packed) ----
#pragma unroll
    for (int c = 0; c < 4; c++) {
        const unsigned int* __restrict__ pc =
            (const unsigned int*)(g_f1 + ((n * Cc + c) << 16)) + t;  // word t of row j at pc[j<<6]
        unsigned int rm3 = (h >= 3)   ? __ldg(pc + ((h - 3) << 6)) : cI;
        unsigned int rm2 = (h >= 2)   ? __ldg(pc + ((h - 2) << 6)) : cI;
        unsigned int rm1 = (h >= 1)   ? __ldg(pc + ((h - 1) << 6)) : cI;
        unsigned int rr0 =              __ldg(pc + ( h      << 6));
        unsigned int rp1 = (h <= 254) ? __ldg(pc + ((h + 1) << 6)) : cI;
        unsigned int rp2 = (h <= 253) ? __ldg(pc + ((h + 2) << 6)) : cI;
        unsigned int rp3 = (h <= 252) ? __ldg(pc + ((h + 3) << 6)) : cI;

        unsigned int acc = rr0;
        acc = __vminu4(acc, __vaddus4(__vminu4(rm1, rp1), c1));
        acc = __vminu4(acc, __vaddus4(__vminu4(rm2, rp2), c4));
        acc = __vminu4(acc, __vaddus4(__vminu4(rm3, rp3), c9));

        unsigned int mask = __vcmpgtu4(acc, cT);
        if (mask) {                            // rare exact fallback per byte
#pragma unroll
            for (int k = 0; k < 4; k++) {
                if ((mask >> (8 * k)) & 0xFFu) {
                    float m = exact_f2(n, c, h, w0 + k);
                    unsigned int b = (unsigned int)fminf(m, 255.0f);
                    acc = (acc & ~(0xFFu << (8 * k))) | (b << (8 * k));
                }
            }
        }
        s_f2[r][c][t] = acc;
    }
    __syncthreads();

    // ---- Phase 2: W-direction (packed, byte-shifted) + softmax ----
    float se[4]  = {0.f, 0.f, 0.f, 0.f};
    float sed[4] = {0.f, 0.f, 0.f, 0.f};
    float sd[4]  = {0.f, 0.f, 0.f, 0.f};
    int pbase = n * CHW + (h << 8) + w0;

#pragma unroll
    for (int c = 0; c < 4; c++) {
        unsigned int cur  = s_f2[r][c][t];
        unsigned int prev = (t > 0)  ? s_f2[r][c][t - 1] : cI;
        unsigned int next = (t < 63) ? s_f2[r][c][t + 1] : cI;

        unsigned int acc = cur;
        unsigned int l1 = __byte_perm(prev, cur, 0x6543), q1 = __byte_perm(cur, next, 0x4321);
        acc = __vminu4(acc, __vaddus4(__vminu4(l1, q1), c1));
        unsigned int l2 = __byte_perm(prev, cur, 0x5432), q2 = __byte_perm(cur, next, 0x5432);
        acc = __vminu4(acc, __vaddus4(__vminu4(l2, q2), c4));
        unsigned int l3 = __byte_perm(prev, cur, 0x4321), q3 = __byte_perm(cur, next, 0x6543);
        acc = __vminu4(acc, __vaddus4(__vminu4(l3, q3), c9));

        float d0, d1, d2, d3;
        unsigned int mask = __vcmpgtu4(acc, cT);
        if (!mask) {
            d0 = sq_tab[acc & 0xFFu];
            d1 = sq_tab[(acc >> 8) & 0xFFu];
            d2 = sq_tab[(acc >> 16) & 0xFFu];
            d3 = sq_tab[(acc >> 24) & 0xFFu];
        } else {                                // astronomically rare exact fallback
            float dv[4];
#pragma unroll
            for (int k = 0; k < 4; k++) {
                unsigned int b = (acc >> (8 * k)) & 0xFFu;
                if (b <= 16u) {
                    dv[k] = sq_tab[b];
                } else {
                    float m = INFV;
                    for (int j = 0; j < Ww; j++) {
                        float dj = (float)(j - (w0 + k));
                        m = fminf(m, fmaf(dj, dj, exact_f2(n, c, h, j)));
                    }
                    dv[k] = sqrtf(m);
                }
            }
            d0 = dv[0]; d1 = dv[1]; d2 = dv[2]; d3 = dv[3];
        }

        float4 x4 = *(const float4*)(pred + pbase + c * HW);
        float e0 = __expf(x4.x), e1 = __expf(x4.y), e2 = __expf(x4.z), e3 = __expf(x4.w);
        se[0]  += e0;      se[1]  += e1;      se[2]  += e2;      se[3]  += e3;
        sed[0] += e0 * d0; sed[1] += e1 * d1; sed[2] += e2 * d2; sed[3] += e3 * d3;
        sd[0]  += d0;      sd[1]  += d1;      sd[2]  += d2;      sd[3]  += d3;
    }

    float num = __fdividef(sed[0], se[0]) + __fdividef(sed[1], se[1]) +
                __fdividef(sed[2], se[2]) + __fdividef(sed[3], se[3]);
    float den = sd[0] + sd[1] + sd[2] + sd[3];

    // ---- block reduce ----
#pragma unroll
    for (int o = 16; o; o >>= 1) {
        num += __shfl_xor_sync(0xFFFFFFFFu, num, o);
        den += __shfl_xor_sync(0xFFFFFFFFu, den, o);
    }
    int lane = tid & 31, wid = tid >> 5;
    if (lane == 0) { rnum[wid] = num; rden[wid] = den; }
    __syncthreads();
    if (wid == 0) {
        num = (lane < 8) ? rnum[lane] : 0.f;
        den = (lane < 8) ? rden[lane] : 0.f;
#pragma unroll
        for (int o = 4; o; o >>= 1) {
            num += __shfl_xor_sync(0xFFFFFFFFu, num, o);
            den += __shfl_xor_sync(0xFFFFFFFFu, den, o);
        }
        if (lane == 0) g_part[blockIdx.x] = make_float2(num, den);
    }

    // ---- last-block final reduction ----
    __threadfence();
    if (threadIdx.x == 0) {
        unsigned int prevc = atomicAdd(&g_ctr, 1u);
        s_last = (prevc == (unsigned int)(NBLK - 1));
    }
    __syncthreads();
    if (!s_last) return;

    __shared__ double snum[8], sden[8];
    double dn = 0.0, dd = 0.0;
#pragma unroll
    for (int q = 0; q < NBLK / 256; q++) {
        float2 p = g_part[q * 256 + tid];
        dn += (double)p.x;
        dd += (double)p.y;
    }
#pragma unroll
    for (int o = 16; o; o >>= 1) {
        dn += __shfl_xor_sync(0xFFFFFFFFu, dn, o);
        dd += __shfl_xor_sync(0xFFFFFFFFu, dd, o);
    }
    if (lane == 0) { snum[wid] = dn; sden[wid] = dd; }
    __syncthreads();
    if (wid == 0) {
        dn = (lane < 8) ? snum[lane] : 0.0;
        dd = (lane < 8) ? sden[lane] : 0.0;
#pragma unroll
        for (int o = 4; o; o >>= 1) {
            dn += __shfl_xor_sync(0xFFFFFFFFu, dn, o);
            dd += __shfl_xor_sync(0xFFFFFFFFu, dd, o);
        }
        if (lane == 0) out[0] = (float)(dn / (dd + 1e-10));
    }
}

// ---------------------------------------------------------------------------
extern "C" void kernel_launch(void* const* d_in, const int* in_sizes, int n_in,
                              void* d_out, int out_size) {
    const float* pred = (const float*)d_in[0];
    const int*   tgt  = (const int*)d_in[1];
    float*       out  = (float*)d_out;

    k_cpass<<<(Nn * HW / 4) / 256, 256>>>(tgt);
    k_main<<<NBLK, 256>>>(pred, out);
}

// round 5
// speedup vs baseline: 5.3584x; 1.1445x over previous
#include <cuda_runtime.h>
#include <cuda_bf16.h>

// Problem dims (fixed by setup_inputs)
#define Nn 16
#define Cc 4
#define Hh 256
#define Ww 256
#define HW  (Hh * Ww)       // 65536
#define CHW (Cc * HW)       // 262144
#define TOT (Nn * CHW)      // 4194304
#define INFV 1.0e10f
#define NBLK 1024           // main-pass blocks (4 rows each)

// Scratch (device globals: no allocation allowed)
__device__ unsigned char g_f1[TOT];     // after C pass: {0,1,4,9, 255=INF}
__device__ float2 g_part[NBLK];         // per-block (num, den) partials
__device__ unsigned int g_ctr;          // last-block counter (reset by k_cpass)

// ---------------------------------------------------------------------------
// C pass: f1[c] = min_{c'} (c-c')^2 + (t[c']!=0 ? 0 : INF), packed u8.
__global__ void k_cpass(const int* __restrict__ tgt) {
    int idx = blockIdx.x * blockDim.x + threadIdx.x;   // over N*H*W/4
    if (idx == 0) g_ctr = 0u;
    int n   = idx >> 14;
    int rem = idx & 16383;
    int base = n * CHW + (rem << 2);

    int4 a0 = *(const int4*)(tgt + base         );
    int4 a1 = *(const int4*)(tgt + base +     HW);
    int4 a2 = *(const int4*)(tgt + base + 2 * HW);
    int4 a3 = *(const int4*)(tgt + base + 3 * HW);

    uchar4 o0, o1, o2, o3;
#pragma unroll
    for (int k = 0; k < 4; k++) {
        bool t0 = ((&a0.x)[k]) != 0;
        bool t1 = ((&a1.x)[k]) != 0;
        bool t2 = ((&a2.x)[k]) != 0;
        bool t3 = ((&a3.x)[k]) != 0;
        (&o0.x)[k] = t0 ? 0 : (t1 ? 1 : (t2 ? 4 : (t3 ? 9 : 255)));
        (&o1.x)[k] = t1 ? 0 : ((t0 || t2) ? 1 : (t3 ? 4 : 255));
        (&o2.x)[k] = t2 ? 0 : ((t1 || t3) ? 1 : (t0 ? 4 : 255));
        (&o3.x)[k] = t3 ? 0 : (t2 ? 1 : (t1 ? 4 : (t0 ? 9 : 255)));
    }
    *(uchar4*)(g_f1 + base         ) = o0;
    *(uchar4*)(g_f1 + base +     HW) = o1;
    *(uchar4*)(g_f1 + base + 2 * HW) = o2;
    *(uchar4*)(g_f1 + base + 3 * HW) = o3;
}

// ---------------------------------------------------------------------------
__device__ __forceinline__ float f1_at(int n, int c, int h, int w) {
    unsigned char v = g_f1[((n * Cc + c) << 16) + (h << 8) + w];
    return (v == 255u) ? INFV : (float)v;
}

// Exact H-direction transform at one (n,c,h,w): window + rare full column scan.
__device__ float exact_f2(int n, int c, int h, int w) {
    float m = INFV;
    int j0 = h - 3 < 0 ? 0 : h - 3;
    int j1 = h + 3 > 255 ? 255 : h + 3;
    for (int j = j0; j <= j1; j++) {
        float dj = (float)(j - h);
        m = fminf(m, fmaf(dj, dj, f1_at(n, c, j, w)));
    }
    if (m > 16.0f) {
        m = INFV;
        for (int j = 0; j < Hh; j++) {
            float dj = (float)(j - h);
            m = fminf(m, fmaf(dj, dj, f1_at(n, c, j, w)));
        }
    }
    return m;
}

// Cold: fix bytes > 16 in a packed H-pass word via exact recompute (clamped
// to 255; an underestimated clamp can never falsely win a <=16 W-window min,
// and any >16 W result triggers the full W recompute below).
__device__ __noinline__ unsigned int fix_h_word(unsigned int acc, int n, int c,
                                                int h, int w0) {
#pragma unroll
    for (int k = 0; k < 4; k++) {
        if (((acc >> (8 * k)) & 0xFFu) > 16u) {
            float m = exact_f2(n, c, h, w0 + k);
            unsigned int b = (unsigned int)fminf(m, 255.0f);
            acc = (acc & ~(0xFFu << (8 * k))) | (b << (8 * k));
        }
    }
    return acc;
}

// Cold: recompute one thread's whole (4-pixel x 4-class) contribution exactly.
__device__ __noinline__ void recompute_unit(int n, int h, int w0,
                                            const float* __restrict__ pred,
                                            float& num, float& den) {
    num = 0.f; den = 0.f;
    for (int k = 0; k < 4; k++) {
        int w = w0 + k;
        float d[4], e[4];
        for (int c = 0; c < 4; c++) {
            float m = INFV;
            int j0 = w - 3 < 0 ? 0 : w - 3;
            int j1 = w + 3 > 255 ? 255 : w + 3;
            for (int j = j0; j <= j1; j++) {
                float dj = (float)(j - w);
                m = fminf(m, fmaf(dj, dj, exact_f2(n, c, h, j)));
            }
            if (m > 16.0f) {
                m = INFV;
                for (int j = 0; j < Ww; j++) {
                    float dj = (float)(j - w);
                    m = fminf(m, fmaf(dj, dj, exact_f2(n, c, h, j)));
                }
            }
            d[c] = sqrtf(m);
            e[c] = __expf(pred[n * CHW + c * HW + (h << 8) + w]);
        }
        float es = e[0] + e[1] + e[2] + e[3];
        num += (e[0] * d[0] + e[1] * d[1] + e[2] * d[2] + e[3] * d[3]) / es;
        den += d[0] + d[1] + d[2] + d[3];
    }
}

// byte k of packed word -> float, then approx sqrt (exact enough for ints 0..16)
__device__ __forceinline__ float byte_sqrt(unsigned int w, int k) {
    float fb = __uint_as_float(__byte_perm(w, 0x4B000000u, 0x7440u + k)) - 8388608.0f;
    float r;
    asm("sqrt.approx.f32 %0, %1;" : "=f"(r) : "f"(fb));
    return r;
}

// ---------------------------------------------------------------------------
// Main pass. Block = 4 consecutive (n,h) rows. Phase 1: 256 threads = (class,
// word); each rolls 10 row-words through registers to produce 4 H-pass words.
// Phase 2: 256 threads = (row, word); packed W-window + softmax + reduction.
// Packed-u8 min-plus is exact whenever the byte <= 16 (outside-window cost
// >= 16; saturation at 255 only ever produces >16 bytes, which are fixed or
// fully recomputed on the cold paths).
__global__ void __launch_bounds__(256, 6) k_main(const float* __restrict__ pred,
                                                 float* __restrict__ out) {
    __shared__ unsigned int s_f2[4][4][64];   // [class][row][word]
    __shared__ float rnum[8], rden[8];
    __shared__ bool  s_last;

    const unsigned int c1 = 0x01010101u, c4 = 0x04040404u, c9 = 0x09090909u;
    const unsigned int cI = 0xFFFFFFFFu, cT = 0x10101010u;

    int tid = threadIdx.x;
    int n = blockIdx.x >> 6;
    int h0 = (blockIdx.x & 63) << 2;

    // ---- Phase 1: H-direction, register rolling ----
    {
        int c = tid >> 6, t = tid & 63;
        const unsigned int* __restrict__ pc =
            (const unsigned int*)(g_f1 + ((n * Cc + c) << 16)) + t;
        unsigned int v[10];
#pragma unroll
        for (int s = 0; s < 10; s++) {
            int j = h0 - 3 + s;
            unsigned int vv = cI;
            if ((unsigned)j < 256u) vv = __ldg(pc + (j << 6));
            v[s] = vv;
        }
        unsigned int outw[4], any = 0u;
#pragma unroll
        for (int r = 0; r < 4; r++) {
            unsigned int acc = v[r + 3];
            acc = __vminu4(acc, __vaddus4(__vminu4(v[r + 2], v[r + 4]), c1));
            acc = __vminu4(acc, __vaddus4(__vminu4(v[r + 1], v[r + 5]), c4));
            acc = __vminu4(acc, __vaddus4(__vminu4(v[r    ], v[r + 6]), c9));
            any |= __vcmpgtu4(acc, cT);
            outw[r] = acc;
        }
        if (any) {     // cold
#pragma unroll
            for (int r = 0; r < 4; r++)
                outw[r] = fix_h_word(outw[r], n, c, h0 + r, t << 2);
        }
#pragma unroll
        for (int r = 0; r < 4; r++)
            s_f2[c][r][t] = outw[r];
    }
    __syncthreads();

    // ---- Phase 2: W-direction + softmax ----
    float num, den;
    {
        int row = tid >> 6, t = tid & 63;
        int h = h0 + row, w0 = t << 2;
        int pbase = n * CHW + (h << 8) + w0;

        float se[4]  = {0.f, 0.f, 0.f, 0.f};
        float sed[4] = {0.f, 0.f, 0.f, 0.f};
        float sd[4]  = {0.f, 0.f, 0.f, 0.f};
        unsigned int any = 0u;

#pragma unroll
        for (int c = 0; c < 4; c++) {
            unsigned int cur  = s_f2[c][row][t];
            unsigned int prev = (t > 0)  ? s_f2[c][row][t - 1] : cI;
            unsigned int next = (t < 63) ? s_f2[c][row][t + 1] : cI;

            unsigned int acc = cur;
            unsigned int l1 = __byte_perm(prev, cur, 0x6543), q1 = __byte_perm(cur, next, 0x4321);
            acc = __vminu4(acc, __vaddus4(__vminu4(l1, q1), c1));
            unsigned int l2 = __byte_perm(prev, cur, 0x5432), q2 = __byte_perm(cur, next, 0x5432);
            acc = __vminu4(acc, __vaddus4(__vminu4(l2, q2), c4));
            unsigned int l3 = __byte_perm(prev, cur, 0x4321), q3 = __byte_perm(cur, next, 0x6543);
            acc = __vminu4(acc, __vaddus4(__vminu4(l3, q3), c9));
            any |= __vcmpgtu4(acc, cT);

            float d0 = byte_sqrt(acc, 0);
            float d1 = byte_sqrt(acc, 1);
            float d2 = byte_sqrt(acc, 2);
            float d3 = byte_sqrt(acc, 3);

            float4 x4 = *(const float4*)(pred + pbase + c * HW);
            float e0 = __expf(x4.x), e1 = __expf(x4.y), e2 = __expf(x4.z), e3 = __expf(x4.w);
            se[0]  += e0;      se[1]  += e1;      se[2]  += e2;      se[3]  += e3;
            sed[0] += e0 * d0; sed[1] += e1 * d1; sed[2] += e2 * d2; sed[3] += e3 * d3;
            sd[0]  += d0;      sd[1]  += d1;      sd[2]  += d2;      sd[3]  += d3;
        }

        num = __fdividef(sed[0], se[0]) + __fdividef(sed[1], se[1]) +
              __fdividef(sed[2], se[2]) + __fdividef(sed[3], se[3]);
        den = sd[0] + sd[1] + sd[2] + sd[3];

        if (any)       // astronomically cold: redo this thread's unit exactly
            recompute_unit(n, h, w0, pred, num, den);
    }

    // ---- block reduce ----
#pragma unroll
    for (int o = 16; o; o >>= 1) {
        num += __shfl_xor_sync(0xFFFFFFFFu, num, o);
        den += __shfl_xor_sync(0xFFFFFFFFu, den, o);
    }
    int lane = tid & 31, wid = tid >> 5;
    if (lane == 0) { rnum[wid] = num; rden[wid] = den; }
    __syncthreads();
    if (wid == 0) {
        num = (lane < 8) ? rnum[lane] : 0.f;
        den = (lane < 8) ? rden[lane] : 0.f;
#pragma unroll
        for (int o = 4; o; o >>= 1) {
            num += __shfl_xor_sync(0xFFFFFFFFu, num, o);
            den += __shfl_xor_sync(0xFFFFFFFFu, den, o);
        }
        if (lane == 0) g_part[blockIdx.x] = make_float2(num, den);
    }

    // ---- last-block final reduction ----
    __threadfence();
    if (threadIdx.x == 0) {
        unsigned int prevc = atomicAdd(&g_ctr, 1u);
        s_last = (prevc == (unsigned int)(NBLK - 1));
    }
    __syncthreads();
    if (!s_last) return;

    __shared__ double snum[8], sden[8];
    double dn = 0.0, dd = 0.0;
#pragma unroll
    for (int q = 0; q < NBLK / 256; q++) {
        float2 p = g_part[q * 256 + tid];
        dn += (double)p.x;
        dd += (double)p.y;
    }
#pragma unroll
    for (int o = 16; o; o >>= 1) {
        dn += __shfl_xor_sync(0xFFFFFFFFu, dn, o);
        dd += __shfl_xor_sync(0xFFFFFFFFu, dd, o);
    }
    if (lane == 0) { snum[wid] = dn; sden[wid] = dd; }
    __syncthreads();
    if (wid == 0) {
        dn = (lane < 8) ? snum[lane] : 0.0;
        dd = (lane < 8) ? sden[lane] : 0.0;
#pragma unroll
        for (int o = 4; o; o >>= 1) {
            dn += __shfl_xor_sync(0xFFFFFFFFu, dn, o);
            dd += __shfl_xor_sync(0xFFFFFFFFu, dd, o);
        }
        if (lane == 0) out[0] = (float)(dn / (dd + 1e-10));
    }
}

// ---------------------------------------------------------------------------
extern "C" void kernel_launch(void* const* d_in, const int* in_sizes, int n_in,
                              void* d_out, int out_size) {
    const float* pred = (const float*)d_in[0];
    const int*   tgt  = (const int*)d_in[1];
    float*       out  = (float*)d_out;

    k_cpass<<<(Nn * HW / 4) / 256, 256>>>(tgt);
    k_main<<<NBLK, 256>>>(pred, out);
}

// round 6
// speedup vs baseline: 6.5450x; 1.2215x over previous
#include <cuda_runtime.h>
#include <cuda_bf16.h>
#include <cuda_fp16.h>

// Problem dims (fixed by setup_inputs)
#define Nn 16
#define Cc 4
#define Hh 256
#define Ww 256
#define HW  (Hh * Ww)       // 65536
#define CHW (Cc * HW)       // 262144
#define TOT (Nn * CHW)      // 4194304
#define INFV 1.0e10f
#define NBLK 1024           // main-pass blocks (4 rows each)

// Scratch (device globals: no allocation allowed)
__device__ __half g_f1h[TOT];           // after C pass: {0,1,4,9, 255=INF} as half
__device__ float2 g_part[NBLK];         // per-block (num, den) partials
__device__ unsigned int g_ctr;          // last-block counter (reset by k_cpass)

__device__ __forceinline__ __half2 U2H(unsigned int u) { return *reinterpret_cast<__half2*>(&u); }
__device__ __forceinline__ unsigned int H2U(__half2 h)  { return *reinterpret_cast<unsigned int*>(&h); }

// ---------------------------------------------------------------------------
// C pass: f1[c] = min_{c'} (c-c')^2 + (t[c']!=0 ? 0 : INF), written as half.
// Thread = 8 w-pixels x 4 classes. 8 LDG.128 in, 4 STG.128 out.
__global__ void k_cpass(const int* __restrict__ tgt) {
    int idx = blockIdx.x * blockDim.x + threadIdx.x;   // over N*H*W/8 = 131072
    if (idx == 0) g_ctr = 0u;
    int n   = idx >> 13;
    int rem = idx & 8191;
    int base = n * CHW + (rem << 3);

    int4 a0a = *(const int4*)(tgt + base          ), a0b = *(const int4*)(tgt + base           + 4);
    int4 a1a = *(const int4*)(tgt + base +     HW ), a1b = *(const int4*)(tgt + base +     HW  + 4);
    int4 a2a = *(const int4*)(tgt + base + 2 * HW ), a2b = *(const int4*)(tgt + base + 2 * HW  + 4);
    int4 a3a = *(const int4*)(tgt + base + 3 * HW ), a3b = *(const int4*)(tgt + base + 3 * HW  + 4);

    float f0[8], f1[8], f2[8], f3[8];
#pragma unroll
    for (int k = 0; k < 8; k++) {
        bool t0 = ((k < 4) ? (&a0a.x)[k] : (&a0b.x)[k - 4]) != 0;
        bool t1 = ((k < 4) ? (&a1a.x)[k] : (&a1b.x)[k - 4]) != 0;
        bool t2 = ((k < 4) ? (&a2a.x)[k] : (&a2b.x)[k - 4]) != 0;
        bool t3 = ((k < 4) ? (&a3a.x)[k] : (&a3b.x)[k - 4]) != 0;
        f0[k] = t0 ? 0.f : (t1 ? 1.f : (t2 ? 4.f : (t3 ? 9.f : 255.f)));
        f1[k] = t1 ? 0.f : ((t0 || t2) ? 1.f : (t3 ? 4.f : 255.f));
        f2[k] = t2 ? 0.f : ((t1 || t3) ? 1.f : (t0 ? 4.f : 255.f));
        f3[k] = t3 ? 0.f : (t2 ? 1.f : (t1 ? 4.f : (t0 ? 9.f : 255.f)));
    }
    uint4 o;
    o = make_uint4(H2U(__floats2half2_rn(f0[0], f0[1])), H2U(__floats2half2_rn(f0[2], f0[3])),
                   H2U(__floats2half2_rn(f0[4], f0[5])), H2U(__floats2half2_rn(f0[6], f0[7])));
    *(uint4*)(g_f1h + base         ) = o;
    o = make_uint4(H2U(__floats2half2_rn(f1[0], f1[1])), H2U(__floats2half2_rn(f1[2], f1[3])),
                   H2U(__floats2half2_rn(f1[4], f1[5])), H2U(__floats2half2_rn(f1[6], f1[7])));
    *(uint4*)(g_f1h + base +     HW) = o;
    o = make_uint4(H2U(__floats2half2_rn(f2[0], f2[1])), H2U(__floats2half2_rn(f2[2], f2[3])),
                   H2U(__floats2half2_rn(f2[4], f2[5])), H2U(__floats2half2_rn(f2[6], f2[7])));
    *(uint4*)(g_f1h + base + 2 * HW) = o;
    o = make_uint4(H2U(__floats2half2_rn(f3[0], f3[1])), H2U(__floats2half2_rn(f3[2], f3[3])),
                   H2U(__floats2half2_rn(f3[4], f3[5])), H2U(__floats2half2_rn(f3[6], f3[7])));
    *(uint4*)(g_f1h + base + 3 * HW) = o;
}

// ---------------------------------------------------------------------------
__device__ __forceinline__ float f1_at(int n, int c, int h, int w) {
    float v = __half2float(g_f1h[((n * Cc + c) << 16) + (h << 8) + w]);
    return (v >= 255.f) ? INFV : v;
}

// Exact H-direction transform at one (n,c,h,w): window + rare full column scan.
__device__ float exact_f2(int n, int c, int h, int w) {
    float m = INFV;
    int j0 = h - 3 < 0 ? 0 : h - 3;
    int j1 = h + 3 > 255 ? 255 : h + 3;
    for (int j = j0; j <= j1; j++) {
        float dj = (float)(j - h);
        m = fminf(m, fmaf(dj, dj, f1_at(n, c, j, w)));
    }
    if (m > 16.0f) {
        m = INFV;
        for (int j = 0; j < Hh; j++) {
            float dj = (float)(j - h);
            m = fminf(m, fmaf(dj, dj, f1_at(n, c, j, w)));
        }
    }
    return m;
}

// Cold: recompute one thread's whole (4-pixel x 4-class) contribution exactly.
__device__ __noinline__ void recompute_unit(int n, int h, int w0,
                                            const float* __restrict__ pred,
                                            float& num, float& den) {
    num = 0.f; den = 0.f;
    for (int k = 0; k < 4; k++) {
        int w = w0 + k;
        float d[4], e[4];
        for (int c = 0; c < 4; c++) {
            float m = INFV;
            int j0 = w - 3 < 0 ? 0 : w - 3;
            int j1 = w + 3 > 255 ? 255 : w + 3;
            for (int j = j0; j <= j1; j++) {
                float dj = (float)(j - w);
                m = fminf(m, fmaf(dj, dj, exact_f2(n, c, h, j)));
            }
            if (m > 16.0f) {
                m = INFV;
                for (int j = 0; j < Ww; j++) {
                    float dj = (float)(j - w);
                    m = fminf(m, fmaf(dj, dj, exact_f2(n, c, h, j)));
                }
            }
            d[c] = sqrtf(m);
            e[c] = __expf(pred[n * CHW + c * HW + (h << 8) + w]);
        }
        float es = e[0] + e[1] + e[2] + e[3];
        num += (e[0] * d[0] + e[1] * d[1] + e[2] * d[2] + e[3] * d[3]) / es;
        den += d[0] + d[1] + d[2] + d[3];
    }
}

__device__ __forceinline__ float fsqrt_approx(float x) {
    float r;
    asm("sqrt.approx.f32 %0, %1;" : "=f"(r) : "f"(x));
    return r;
}

// ---------------------------------------------------------------------------
// Main pass. Block = 4 consecutive (n,h) rows.
// Phase 1: thread = (class, 4-px column); rolls 10 half2-pair rows through
//          registers -> 4 H-pass word-pairs into padded smem. Native HMNMX2/
//          HADD2 min-plus; no cold path needed here (overestimates of values
//          whose true min > 16 are caught by the phase-2 cold check).
// Phase 2: thread = (row, 4-px); W window via PRMT half-shifts + softmax +
//          block reduce. Single cold check -> exact recompute of the unit.
// Exactness: outside-window cost >= 16, so any result <= 16 is exact; any
// pixel whose true value > 16 yields acc > 16 and trips the cold path.
__global__ void __launch_bounds__(256, 6) k_main(const float* __restrict__ pred,
                                                 float* __restrict__ out) {
    __shared__ unsigned int s_f2[4][4][132];  // [class][row][2 + 128 + 2] half2 words
    __shared__ float rnum[8], rden[8];
    __shared__ bool  s_last;

    const __half2 C1 = __float2half2_rn(1.0f);
    const __half2 C4 = __float2half2_rn(4.0f);
    const __half2 C9 = __float2half2_rn(9.0f);
    const unsigned int INFW = 0x5BF85BF8u;    // half2(255, 255)

    int tid = threadIdx.x;
    int n = blockIdx.x >> 6;
    int h0 = (blockIdx.x & 63) << 2;

    // borders
    if (tid < 64) {
        int c = tid >> 4, r = (tid >> 2) & 3, b = tid & 3;
        s_f2[c][r][b < 2 ? b : 128 + b] = INFW;
    }

    // ---- Phase 1: H-direction (native half2 min-plus) ----
    {
        int c = tid >> 6, t = tid & 63;
        const __half* __restrict__ pc = g_f1h + ((n * Cc + c) << 16) + (t << 2);
        uint2 v[10];
#pragma unroll
        for (int s = 0; s < 10; s++) {
            int j = h0 - 3 + s;
            v[s] = ((unsigned)j < 256u) ? *(const uint2*)(pc + (j << 8))
                                        : make_uint2(INFW, INFW);
        }
#pragma unroll
        for (int r = 0; r < 4; r++) {
            __half2 aA = U2H(v[r + 3].x), aB = U2H(v[r + 3].y);
            aA = __hmin2(aA, __hadd2(__hmin2(U2H(v[r + 2].x), U2H(v[r + 4].x)), C1));
            aB = __hmin2(aB, __hadd2(__hmin2(U2H(v[r + 2].y), U2H(v[r + 4].y)), C1));
            aA = __hmin2(aA, __hadd2(__hmin2(U2H(v[r + 1].x), U2H(v[r + 5].x)), C4));
            aB = __hmin2(aB, __hadd2(__hmin2(U2H(v[r + 1].y), U2H(v[r + 5].y)), C4));
            aA = __hmin2(aA, __hadd2(__hmin2(U2H(v[r    ].x), U2H(v[r + 6].x)), C9));
            aB = __hmin2(aB, __hadd2(__hmin2(U2H(v[r    ].y), U2H(v[r + 6].y)), C9));
            s_f2[c][r][2 + 2 * t    ] = H2U(aA);
            s_f2[c][r][2 + 2 * t + 1] = H2U(aB);
        }
    }
    __syncthreads();

    // ---- Phase 2: W-direction + softmax ----
    float num, den;
    {
        int row = tid >> 6, t = tid & 63;
        int h = h0 + row, w0 = t << 2;
        int pbase = n * CHW + (h << 8) + w0;

        float se[4]  = {0.f, 0.f, 0.f, 0.f};
        float sed[4] = {0.f, 0.f, 0.f, 0.f};
        float sd[4]  = {0.f, 0.f, 0.f, 0.f};
        __half2 hmx = __float2half2_rn(0.0f);

#pragma unroll
        for (int c = 0; c < 4; c++) {
            const unsigned int* __restrict__ sb = s_f2[c][row];
            uint2 wa = *(const uint2*)(sb + 2 * t);      // logical words 2t-2, 2t-1
            uint2 wb = *(const uint2*)(sb + 2 * t + 2);  // 2t, 2t+1 (center)
            uint2 wc = *(const uint2*)(sb + 2 * t + 4);  // 2t+2, 2t+3

            unsigned int p01 = __byte_perm(wa.x, wa.y, 0x5432);
            unsigned int p12 = __byte_perm(wa.y, wb.x, 0x5432);
            unsigned int p23 = __byte_perm(wb.x, wb.y, 0x5432);
            unsigned int p34 = __byte_perm(wb.y, wc.x, 0x5432);
            unsigned int p45 = __byte_perm(wc.x, wc.y, 0x5432);

            __half2 aA = U2H(wb.x), aB = U2H(wb.y);
            aA = __hmin2(aA, __hadd2(__hmin2(U2H(p12), U2H(p23)), C1));
            aB = __hmin2(aB, __hadd2(__hmin2(U2H(p23), U2H(p34)), C1));
            aA = __hmin2(aA, __hadd2(__hmin2(U2H(wa.y), U2H(wb.y)), C4));
            aB = __hmin2(aB, __hadd2(__hmin2(U2H(wb.x), U2H(wc.x)), C4));
            aA = __hmin2(aA, __hadd2(__hmin2(U2H(p01), U2H(p34)), C9));
            aB = __hmin2(aB, __hadd2(__hmin2(U2H(p12), U2H(p45)), C9));
            hmx = __hmax2(hmx, __hmax2(aA, aB));

            float2 fA = __half22float2(aA), fB = __half22float2(aB);
            float d0 = fsqrt_approx(fA.x), d1 = fsqrt_approx(fA.y);
            float d2 = fsqrt_approx(fB.x), d3 = fsqrt_approx(fB.y);

            float4 x4 = *(const float4*)(pred + pbase + c * HW);
            float e0 = __expf(x4.x), e1 = __expf(x4.y), e2 = __expf(x4.z), e3 = __expf(x4.w);
            se[0]  += e0;      se[1]  += e1;      se[2]  += e2;      se[3]  += e3;
            sed[0] += e0 * d0; sed[1] += e1 * d1; sed[2] += e2 * d2; sed[3] += e3 * d3;
            sd[0]  += d0;      sd[1]  += d1;      sd[2]  += d2;      sd[3]  += d3;
        }

        num = __fdividef(sed[0], se[0]) + __fdividef(sed[1], se[1]) +
              __fdividef(sed[2], se[2]) + __fdividef(sed[3], se[3]);
        den = sd[0] + sd[1] + sd[2] + sd[3];

        float chk = fmaxf(__half2float(__low2half(hmx)), __half2float(__high2half(hmx)));
        if (chk > 16.0f)     // astronomically cold: redo this unit exactly
            recompute_unit(n, h, w0, pred, num, den);
    }

    // ---- block reduce ----
#pragma unroll
    for (int o = 16; o; o >>= 1) {
        num += __shfl_xor_sync(0xFFFFFFFFu, num, o);
        den += __shfl_xor_sync(0xFFFFFFFFu, den, o);
    }
    int lane = tid & 31, wid = tid >> 5;
    if (lane == 0) { rnum[wid] = num; rden[wid] = den; }
    __syncthreads();
    if (wid == 0) {
        num = (lane < 8) ? rnum[lane] : 0.f;
        den = (lane < 8) ? rden[lane] : 0.f;
#pragma unroll
        for (int o = 4; o; o >>= 1) {
            num += __shfl_xor_sync(0xFFFFFFFFu, num, o);
            den += __shfl_xor_sync(0xFFFFFFFFu, den, o);
        }
        if (lane == 0) g_part[blockIdx.x] = make_float2(num, den);
    }

    // ---- last-block final reduction ----
    __threadfence();
    if (threadIdx.x == 0) {
        unsigned int prevc = atomicAdd(&g_ctr, 1u);
        s_last = (prevc == (unsigned int)(NBLK - 1));
    }
    __syncthreads();
    if (!s_last) return;

    __shared__ double snum[8], sden[8];
    double dn = 0.0, dd = 0.0;
#pragma unroll
    for (int q = 0; q < NBLK / 256; q++) {
        float2 p = g_part[q * 256 + tid];
        dn += (double)p.x;
        dd += (double)p.y;
    }
#pragma unroll
    for (int o = 16; o; o >>= 1) {
        dn += __shfl_xor_sync(0xFFFFFFFFu, dn, o);
        dd += __shfl_xor_sync(0xFFFFFFFFu, dd, o);
    }
    if (lane == 0) { snum[wid] = dn; sden[wid] = dd; }
    __syncthreads();
    if (wid == 0) {
        dn = (lane < 8) ? snum[lane] : 0.0;
        dd = (lane < 8) ? sden[lane] : 0.0;
#pragma unroll
        for (int o = 4; o; o >>= 1) {
            dn += __shfl_xor_sync(0xFFFFFFFFu, dn, o);
            dd += __shfl_xor_sync(0xFFFFFFFFu, dd, o);
        }
        if (lane == 0) out[0] = (float)(dn / (dd + 1e-10));
    }
}

// ---------------------------------------------------------------------------
extern "C" void kernel_launch(void* const* d_in, const int* in_sizes, int n_in,
                              void* d_out, int out_size) {
    const float* pred = (const float*)d_in[0];
    const int*   tgt  = (const int*)d_in[1];
    float*       out  = (float*)d_out;

    k_cpass<<<(Nn * HW / 8) / 256, 256>>>(tgt);
    k_main<<<NBLK, 256>>>(pred, out);
}